// round 12
// baseline (speedup 1.0000x reference)
#include <cuda_runtime.h>
#include <cuda_fp16.h>

#define C_DIM 512
#define N_TOK 4096
#define HEADS 16
#define HDIM  32
// (1/sqrt(32)) * log2(e), folded into wq/bq
#define ALPHA 0.25504448f
#define ONESH2 0x3C003C00u

// ---------------- scratch ----------------
__device__ __half g_qnt[N_TOK * C_DIM];
__device__ __half g_vnt[N_TOK * C_DIM];
__device__ __half g_qt [N_TOK * C_DIM];
__device__ __half g_kt [N_TOK * C_DIM];
__device__ __half g_vt [N_TOK * C_DIM];
__device__ __half g_aot[N_TOK * C_DIM];
__device__ __half g_wh [4 * C_DIM * C_DIM];
__device__ float g_cs[C_DIM], g_cq[C_DIM];

// ---------------- helpers ----------------
__device__ __forceinline__ float ex2(float x) {
    float r; asm("ex2.approx.ftz.f32 %0, %1;" : "=f"(r) : "f"(x)); return r;
}
__device__ __forceinline__ unsigned h2ex2(unsigned x) {
    unsigned r; asm("ex2.approx.f16x2 %0, %1;" : "=r"(r) : "r"(x)); return r;
}
__device__ __forceinline__ unsigned packh2(float lo, float hi) {
    unsigned u; asm("cvt.rn.f16x2.f32 %0, %1, %2;" : "=r"(u) : "f"(hi), "f"(lo)); return u;
}
__device__ __forceinline__ unsigned hsub2(unsigned a, unsigned b) {
    unsigned r; asm("sub.rn.f16x2 %0, %1, %2;" : "=r"(r) : "r"(a), "r"(b)); return r;
}
__device__ __forceinline__ unsigned hmax2(unsigned a, unsigned b) {
    unsigned r; asm("max.f16x2 %0, %1, %2;" : "=r"(r) : "r"(a), "r"(b)); return r;
}
__device__ __forceinline__ unsigned swap16(unsigned a) {
    unsigned r; asm("prmt.b32 %0, %1, %1, 0x1032;" : "=r"(r) : "r"(a)); return r;
}
// f32-accumulator MMA
__device__ __forceinline__ void mma16816(float* d, const unsigned* a, unsigned b0, unsigned b1) {
    asm volatile(
        "mma.sync.aligned.m16n8k16.row.col.f32.f16.f16.f32 "
        "{%0,%1,%2,%3}, {%4,%5,%6,%7}, {%8,%9}, {%0,%1,%2,%3};"
        : "+f"(d[0]), "+f"(d[1]), "+f"(d[2]), "+f"(d[3])
        : "r"(a[0]), "r"(a[1]), "r"(a[2]), "r"(a[3]), "r"(b0), "r"(b1));
}
__device__ __forceinline__ void mma16816_z(float* d, const unsigned* a, unsigned b0, unsigned b1) {
    asm volatile(
        "mma.sync.aligned.m16n8k16.row.col.f32.f16.f16.f32 "
        "{%0,%1,%2,%3}, {%4,%5,%6,%7}, {%8,%9}, {%10,%10,%10,%10};"
        : "=f"(d[0]), "=f"(d[1]), "=f"(d[2]), "=f"(d[3])
        : "r"(a[0]), "r"(a[1]), "r"(a[2]), "r"(a[3]), "r"(b0), "r"(b1), "f"(0.f));
}
// f16-accumulator MMA (2x tensor rate; D = 2 x f16x2 regs)
__device__ __forceinline__ void mma16816h(unsigned* d, const unsigned* a, unsigned b0, unsigned b1) {
    asm volatile(
        "mma.sync.aligned.m16n8k16.row.col.f16.f16.f16.f16 "
        "{%0,%1}, {%2,%3,%4,%5}, {%6,%7}, {%0,%1};"
        : "+r"(d[0]), "+r"(d[1])
        : "r"(a[0]), "r"(a[1]), "r"(a[2]), "r"(a[3]), "r"(b0), "r"(b1));
}
__device__ __forceinline__ void mma16816h_z(unsigned* d, const unsigned* a, unsigned b0, unsigned b1) {
    asm volatile(
        "mma.sync.aligned.m16n8k16.row.col.f16.f16.f16.f16 "
        "{%0,%1}, {%2,%3,%4,%5}, {%6,%7}, {%8,%8};"
        : "=r"(d[0]), "=r"(d[1])
        : "r"(a[0]), "r"(a[1]), "r"(a[2]), "r"(a[3]), "r"(b0), "r"(b1), "r"(0u));
}
__device__ __forceinline__ unsigned su32(const void* p) {
    return (unsigned)__cvta_generic_to_shared(p);
}
__device__ __forceinline__ void ldsm4u(unsigned* r, unsigned a) {
    asm volatile("ldmatrix.sync.aligned.m8n8.x4.shared.b16 {%0,%1,%2,%3}, [%4];"
                 : "=r"(r[0]), "=r"(r[1]), "=r"(r[2]), "=r"(r[3]) : "r"(a));
}
__device__ __forceinline__ void ldsm4tu(unsigned* r, unsigned a) {
    asm volatile("ldmatrix.sync.aligned.m8n8.x4.trans.shared.b16 {%0,%1,%2,%3}, [%4];"
                 : "=r"(r[0]), "=r"(r[1]), "=r"(r[2]), "=r"(r[3]) : "r"(a));
}
__device__ __forceinline__ void cp16(void* smem, const void* gmem) {
    unsigned sa = (unsigned)__cvta_generic_to_shared(smem);
    asm volatile("cp.async.cg.shared.global [%0], [%1], 16;" :: "r"(sa), "l"(gmem) : "memory");
}
#define CP_COMMIT asm volatile("cp.async.commit_group;" ::: "memory")
#define CP_WAIT1  asm volatile("cp.async.wait_group 1;" ::: "memory")
#define CP_WAIT0  asm volatile("cp.async.wait_group 0;" ::: "memory")

// ---------------------------------------------------------------------------
// Fused: per-channel stats (blocks 0..511) + weight fp16 rounding (512..1023).
// ---------------------------------------------------------------------------
__global__ __launch_bounds__(256) void stats_weights(const float* __restrict__ x,
                                                     const float* __restrict__ wq,
                                                     const float* __restrict__ wk,
                                                     const float* __restrict__ wv,
                                                     const float* __restrict__ wo) {
    int b = blockIdx.x;
    if (b < C_DIM) {
        __shared__ float sh[16];
        const float4* p = (const float4*)(x + (size_t)b * N_TOK);
        float s = 0.f, sq = 0.f;
        #pragma unroll
        for (int i = threadIdx.x; i < N_TOK / 4; i += 256) {
            float4 v = p[i];
            s  += (v.x + v.y) + (v.z + v.w);
            sq += v.x * v.x + v.y * v.y + v.z * v.z + v.w * v.w;
        }
        #pragma unroll
        for (int off = 16; off > 0; off >>= 1) {
            s  += __shfl_down_sync(0xffffffffu, s,  off);
            sq += __shfl_down_sync(0xffffffffu, sq, off);
        }
        int wr = threadIdx.x >> 5, lane = threadIdx.x & 31;
        if (lane == 0) { sh[wr] = s; sh[8 + wr] = sq; }
        __syncthreads();
        if (threadIdx.x == 0) {
            float ts = 0.f, tq = 0.f;
            #pragma unroll
            for (int i = 0; i < 8; ++i) { ts += sh[i]; tq += sh[8 + i]; }
            g_cs[b] = ts; g_cq[b] = tq;
        }
    } else {
        int base = (b - C_DIM) * 512;
        #pragma unroll
        for (int it = 0; it < 2; ++it) {
            int i = base + threadIdx.x + it * 256;
            int sel = i >> 16, loc = i & 65535;
            const float4* src = (const float4*)(sel == 0 ? wq : sel == 1 ? wk : sel == 2 ? wv : wo);
            float sc = (sel == 0) ? ALPHA : 1.f;
            float4 v = src[loc];
            uint2 o;
            o.x = packh2(v.x * sc, v.y * sc);
            o.y = packh2(v.z * sc, v.w * sc);
            *(uint2*)&g_wh[(size_t)i * 4] = o;
        }
    }
}

// ---------------------------------------------------------------------------
// GN apply + transpose with inline analytic finalize. grid (N_TOK/64, 4)
// ---------------------------------------------------------------------------
__global__ __launch_bounds__(256) void apply_tr(const float* __restrict__ x,
                                                const float* __restrict__ w,
                                                const float* __restrict__ b) {
    __shared__ float a1s[C_DIM], c1s[C_DIM], avs[C_DIM], cvs[C_DIM];
    __shared__ __half sq[64][132];
    __shared__ __half sv[64][132];
    int tid = threadIdx.x;

    if (tid < 32) {
        int g = tid;
        const float inv = 1.f / (float)N_TOK;
        float m1 = 0.f, E1 = 0.f;
        #pragma unroll
        for (int c = 0; c < 16; ++c) {
            int ch = g * 16 + c;
            m1 += g_cs[ch] * inv;
            E1 += g_cq[ch] * inv;
        }
        m1 *= (1.f / 16.f); E1 *= (1.f / 16.f);
        float is1 = rsqrtf(E1 - m1 * m1 + 1e-6f);
        float m2 = 0.f, E2 = 0.f;
        #pragma unroll
        for (int c = 0; c < 16; ++c) {
            int ch = g * 16 + c;
            float mc = g_cs[ch] * inv, Ec = g_cq[ch] * inv;
            float a1 = w[ch] * is1;
            float c1 = b[ch] - m1 * a1;
            a1s[ch] = a1; c1s[ch] = c1;
            m2 += a1 * mc + c1;
            E2 += a1 * a1 * Ec + 2.f * a1 * c1 * mc + c1 * c1;
        }
        m2 *= (1.f / 16.f); E2 *= (1.f / 16.f);
        float is2 = rsqrtf(E2 - m2 * m2 + 1e-6f);
        #pragma unroll
        for (int c = 0; c < 16; ++c) {
            int ch = g * 16 + c;
            float a2 = w[ch] * is2;
            float c2 = b[ch] - m2 * a2;
            avs[ch] = a2 * a1s[ch];
            cvs[ch] = a2 * c1s[ch] + c2;
        }
    }
    __syncthreads();

    int n0 = blockIdx.x * 64;
    int cc = blockIdx.y;
    #pragma unroll
    for (int i = 0; i < 32; ++i) {
        int idx = tid + i * 256;
        int t = idx & 63, ci = idx >> 6;
        int c = cc * 128 + ci;
        float v = x[(size_t)c * N_TOK + n0 + t];
        sq[t][ci] = __float2half_rn(v * a1s[c] + c1s[c]);
        sv[t][ci] = __float2half_rn(v * avs[c] + cvs[c]);
    }
    __syncthreads();
    #pragma unroll
    for (int i = 0; i < 16; ++i) {
        int idx = tid + i * 256;
        int t = idx >> 6, j = idx & 63;
        __half2 q2 = __halves2half2(sq[t][2 * j], sq[t][2 * j + 1]);
        __half2 v2 = __halves2half2(sv[t][2 * j], sv[t][2 * j + 1]);
        *(__half2*)&g_qnt[(size_t)(n0 + t) * 512 + cc * 128 + 2 * j] = q2;
        *(__half2*)&g_vnt[(size_t)(n0 + t) * 512 + cc * 128 + 2 * j] = v2;
    }
}

// ---------------------------------------------------------------------------
// fp16 GEMM: C[tok][outch] = Xt * W^T + bias (unchanged structure).
// ---------------------------------------------------------------------------
template<int FIN>
__global__ __launch_bounds__(256, 2) void gemm_h(const float* __restrict__ b0p,
                                                 const float* __restrict__ b1p,
                                                 const float* __restrict__ b2p,
                                                 const float* __restrict__ resid,
                                                 float* __restrict__ OutF) {
    __shared__ __half As[2][64 * 40];
    __shared__ __half Bs[2][128 * 40];

    int tid = threadIdx.x;
    int warp = tid >> 5, lane = tid & 31;
    int g = lane >> 2, qq = lane & 3;
    int wm = warp >> 2, wn = warp & 3;
    int m0 = blockIdx.x * 64;
    int n0 = blockIdx.y * 128;

    int z = FIN ? 3 : (int)blockIdx.z;
    const __half* W  = g_wh + (size_t)z * (C_DIM * C_DIM);
    const __half* Xt = FIN ? g_aot : (z == 0 ? g_qnt : g_vnt);
    const float* bias = FIN ? b0p : (z == 0 ? b0p : (z == 1 ? b1p : b2p));
    __half* OutH = z == 0 ? g_qt : (z == 1 ? g_kt : g_vt);

    float acc[2][4][4];
    #pragma unroll
    for (int i = 0; i < 2; ++i)
        #pragma unroll
        for (int j = 0; j < 4; ++j)
            #pragma unroll
            for (int r = 0; r < 4; ++r) acc[i][j][r] = 0.f;

    #define GLOAD(st, k0)                                                        \
    {                                                                            \
        { int m = tid >> 2, q = tid & 3;                                         \
          cp16(&As[st][m * 40 + q * 8], &Xt[(size_t)(m0 + m) * 512 + (k0) + q * 8]); } \
        _Pragma("unroll")                                                        \
        for (int i = 0; i < 2; ++i) {                                            \
            int idx = tid + i * 256; int n = idx >> 2, q = idx & 3;              \
            cp16(&Bs[st][n * 40 + q * 8], &W[(size_t)(n0 + n) * 512 + (k0) + q * 8]); \
        }                                                                        \
    }

    GLOAD(0, 0); CP_COMMIT;

    #pragma unroll 1
    for (int kt = 0; kt < 16; ++kt) {
        int s = kt & 1;
        if (kt < 15) { GLOAD(s ^ 1, (kt + 1) * 32); CP_COMMIT; CP_WAIT1; }
        else         { CP_WAIT0; }
        __syncthreads();

        const unsigned* Au = (const unsigned*)As[s];
        const unsigned* Bu = (const unsigned*)Bs[s];
        #pragma unroll
        for (int kk = 0; kk < 2; ++kk) {
            unsigned a[2][4], bb[4][2];
            #pragma unroll
            for (int mi = 0; mi < 2; ++mi) {
                int r = wm * 32 + mi * 16 + g;
                a[mi][0] = Au[r * 20 + kk * 8 + qq];
                a[mi][1] = Au[(r + 8) * 20 + kk * 8 + qq];
                a[mi][2] = Au[r * 20 + kk * 8 + qq + 4];
                a[mi][3] = Au[(r + 8) * 20 + kk * 8 + qq + 4];
            }
            #pragma unroll
            for (int ni = 0; ni < 4; ++ni) {
                int n = wn * 32 + ni * 8 + g;
                bb[ni][0] = Bu[n * 20 + kk * 8 + qq];
                bb[ni][1] = Bu[n * 20 + kk * 8 + qq + 4];
            }
            #pragma unroll
            for (int mi = 0; mi < 2; ++mi)
                #pragma unroll
                for (int ni = 0; ni < 4; ++ni)
                    mma16816(acc[mi][ni], a[mi], bb[ni][0], bb[ni][1]);
        }
        __syncthreads();
    }
    #undef GLOAD

    const float IS2 = 0.70710678118654752f;
    float bscale = (!FIN && z == 0) ? ALPHA : 1.f;
    #pragma unroll
    for (int mi = 0; mi < 2; ++mi) {
        int t = m0 + wm * 32 + mi * 16 + g;
        #pragma unroll
        for (int ni = 0; ni < 4; ++ni) {
            int ch = n0 + wn * 32 + ni * 8 + 2 * qq;
            float bb0 = bias[ch] * bscale, bb1 = bias[ch + 1] * bscale;
            float c0 = acc[mi][ni][0] + bb0, c1 = acc[mi][ni][1] + bb1;
            float c2 = acc[mi][ni][2] + bb0, c3 = acc[mi][ni][3] + bb1;
            if (FIN) {
                size_t i00 = (size_t)ch * N_TOK + t;
                size_t i10 = (size_t)(ch + 1) * N_TOK + t;
                OutF[i00]     = (c0 + resid[i00])     * IS2;
                OutF[i10]     = (c1 + resid[i10])     * IS2;
                OutF[i00 + 8] = (c2 + resid[i00 + 8]) * IS2;
                OutF[i10 + 8] = (c3 + resid[i10 + 8]) * IS2;
            } else {
                *(unsigned*)&OutH[(size_t)t * 512 + ch]       = packh2(c0, c1);
                *(unsigned*)&OutH[(size_t)(t + 8) * 512 + ch] = packh2(c2, c3);
            }
        }
    }
}

// ---------------------------------------------------------------------------
// Flash attention fp16: CTA = 64 queries x head (4 warps x 16 q-rows).
// 128-key tiles; QK^T in f16-accumulator MMA (2x rate) whose D fragments are
// bit-identical to the PV A-fragments (no packing); f16x2 max/sub/exp;
// ones-MMA l; f32 O accumulators.
// ---------------------------------------------------------------------------
__global__ __launch_bounds__(128, 5) void attn_h() {
    __shared__ __half Ks[2][128 * 40];
    __shared__ __half Vs[2][128 * 40];

    int tid = threadIdx.x;
    int lane = tid & 31;
    int w = tid >> 5;
    int g = lane >> 2, qq = lane & 3;
    int h = blockIdx.y;
    int hb = h * HDIM;
    int q0 = blockIdx.x * 64 + w * 16;

    unsigned qa[2][4];
    #pragma unroll
    for (int kk = 0; kk < 2; ++kk) {
        const __half* qp = &g_qt[(size_t)(q0 + g) * 512 + hb + kk * 16 + 2 * qq];
        qa[kk][0] = *(const unsigned*)qp;
        qa[kk][1] = *(const unsigned*)(qp + 8 * 512);
        qa[kk][2] = *(const unsigned*)(qp + 8);
        qa[kk][3] = *(const unsigned*)(qp + 8 * 512 + 8);
    }

    float o[4][4];
    #pragma unroll
    for (int nd = 0; nd < 4; ++nd)
        #pragma unroll
        for (int e = 0; e < 4; ++e) o[nd][e] = 0.f;
    float m0 = -1e30f, m1 = -1e30f, l0 = 0.f, l1 = 0.f;

    int kfrag = ((lane & 7) * 40 + ((lane >> 3) << 3)) * 2;
    int vfrag = ((lane & 15) * 40 + ((lane >> 4) << 3)) * 2;
    unsigned ksu[2] = { su32(&Ks[0][0]) + kfrag, su32(&Ks[1][0]) + kfrag };
    unsigned vsu[2] = { su32(&Vs[0][0]) + vfrag, su32(&Vs[1][0]) + vfrag };

    #define APRE(st, kt0)                                                        \
    {                                                                            \
        _Pragma("unroll")                                                        \
        for (int i = 0; i < 4; ++i) {                                            \
            int idx = tid + i * 128; int row = idx >> 2, q = idx & 3;            \
            cp16(&Ks[st][row * 40 + q * 8],                                      \
                 &g_kt[(size_t)((kt0) + row) * 512 + hb + q * 8]);               \
            cp16(&Vs[st][row * 40 + q * 8],                                      \
                 &g_vt[(size_t)((kt0) + row) * 512 + hb + q * 8]);               \
        }                                                                        \
    }

    APRE(0, 0); CP_COMMIT;

    #pragma unroll 1
    for (int it = 0; it < 32; ++it) {
        int s = it & 1;
        if (it < 31) { APRE(s ^ 1, (it + 1) * 128); CP_COMMIT; CP_WAIT1; }
        else         { CP_WAIT0; }
        __syncthreads();

        // S = Q K^T (16q x 128k), f16 accumulators.
        // sch[nj][0] = {S[g][2qq],S[g][2qq+1]}, sch[nj][1] = {S[g+8][...]}.
        unsigned sch[16][2];
        #pragma unroll
        for (int nj = 0; nj < 16; ++nj) {
            unsigned kb[4];
            ldsm4u(kb, ksu[s] + nj * (8 * 40 * 2));
            mma16816h_z(sch[nj], qa[0], kb[0], kb[1]);
            mma16816h  (sch[nj], qa[1], kb[2], kb[3]);
        }

        // row max via f16x2 tree + quad shuffles + halfword swap
        unsigned hx0 = sch[0][0], hx1 = sch[0][1];
        #pragma unroll
        for (int nj = 1; nj < 16; ++nj) {
            hx0 = hmax2(hx0, sch[nj][0]);
            hx1 = hmax2(hx1, sch[nj][1]);
        }
        hx0 = hmax2(hx0, __shfl_xor_sync(0xffffffffu, hx0, 1));
        hx0 = hmax2(hx0, __shfl_xor_sync(0xffffffffu, hx0, 2));
        hx1 = hmax2(hx1, __shfl_xor_sync(0xffffffffu, hx1, 1));
        hx1 = hmax2(hx1, __shfl_xor_sync(0xffffffffu, hx1, 2));
        hx0 = hmax2(hx0, swap16(hx0));   // both halves = row-g max
        hx1 = hmax2(hx1, swap16(hx1));   // both halves = row-g+8 max
        float tm0 = __half2float(__ushort_as_half((unsigned short)(hx0 & 0xFFFFu)));
        float tm1 = __half2float(__ushort_as_half((unsigned short)(hx1 & 0xFFFFu)));
        float nm0 = fmaxf(m0, tm0), nm1 = fmaxf(m1, tm1);
        float cr0 = ex2(m0 - nm0), cr1 = ex2(m1 - nm1);
        m0 = nm0; m1 = nm1;
        #pragma unroll
        for (int nd = 0; nd < 4; ++nd) {
            o[nd][0] *= cr0; o[nd][1] *= cr0;
            o[nd][2] *= cr1; o[nd][3] *= cr1;
        }
        unsigned nm00 = packh2(nm0, nm0), nm11 = packh2(nm1, nm1);

        // P = exp2(S - m) in-place (f16x2); fragments are PV A-operands.
        #pragma unroll
        for (int nj = 0; nj < 16; ++nj) {
            sch[nj][0] = h2ex2(hsub2(sch[nj][0], nm00));
            sch[nj][1] = h2ex2(hsub2(sch[nj][1], nm11));
        }

        // l-MMA + PV per 16-key block
        float lacc[4];
        #pragma unroll
        for (int kk = 0; kk < 8; ++kk) {
            unsigned ph[4] = { sch[2*kk][0], sch[2*kk][1], sch[2*kk+1][0], sch[2*kk+1][1] };
            if (kk == 0) mma16816_z(lacc, ph, ONESH2, ONESH2);
            else         mma16816  (lacc, ph, ONESH2, ONESH2);
            unsigned v0[4], v1[4];
            unsigned vb = vsu[s] + kk * (16 * 40 * 2);
            ldsm4tu(v0, vb);
            ldsm4tu(v1, vb + 32);
            mma16816(o[0], ph, v0[0], v0[1]);
            mma16816(o[1], ph, v0[2], v0[3]);
            mma16816(o[2], ph, v1[0], v1[1]);
            mma16816(o[3], ph, v1[2], v1[3]);
        }
        l0 = l0 * cr0 + lacc[0];
        l1 = l1 * cr1 + lacc[2];
        __syncthreads();
    }
    #undef APRE

    float i0 = 1.f / l0, i1 = 1.f / l1;
    #pragma unroll
    for (int nd = 0; nd < 4; ++nd) {
        int d = hb + nd * 8 + 2 * qq;
        *(unsigned*)&g_aot[(size_t)(q0 + g) * 512 + d]     = packh2(o[nd][0] * i0, o[nd][1] * i0);
        *(unsigned*)&g_aot[(size_t)(q0 + g + 8) * 512 + d] = packh2(o[nd][2] * i1, o[nd][3] * i1);
    }
}

// ---------------------------------------------------------------------------
// Launch
// ---------------------------------------------------------------------------
extern "C" void kernel_launch(void* const* d_in, const int* in_sizes, int n_in,
                              void* d_out, int out_size) {
    const float* x   = (const float*)d_in[0];
    const float* gnw = (const float*)d_in[1];
    const float* gnb = (const float*)d_in[2];
    const float* wq  = (const float*)d_in[3];
    const float* bq  = (const float*)d_in[4];
    const float* wk  = (const float*)d_in[5];
    const float* bk  = (const float*)d_in[6];
    const float* wv  = (const float*)d_in[7];
    const float* bv  = (const float*)d_in[8];
    const float* wo  = (const float*)d_in[9];
    const float* bo  = (const float*)d_in[10];
    float* out = (float*)d_out;

    stats_weights<<<1024, 256>>>(x, wq, wk, wv, wo);

    dim3 at(N_TOK / 64, 4);
    apply_tr<<<at, 256>>>(x, gnw, gnb);

    dim3 gqkv(N_TOK / 64, C_DIM / 128, 3);      // 768 CTAs
    gemm_h<0><<<gqkv, 256>>>(bq, bk, bv, nullptr, nullptr);

    dim3 ag(N_TOK / 64, HEADS);                 // (64, 16) = 1024 CTAs
    attn_h<<<ag, 128>>>();

    dim3 go(N_TOK / 64, C_DIM / 128, 1);        // 256 CTAs
    gemm_h<1><<<go, 256>>>(bo, nullptr, nullptr, x, out);
}

// round 14
// speedup vs baseline: 1.5342x; 1.5342x over previous
#include <cuda_runtime.h>
#include <cuda_fp16.h>

#define C_DIM 512
#define N_TOK 4096
#define HEADS 16
#define HDIM  32
// (1/sqrt(32)) * log2(e), folded into wq/bq
#define ALPHA 0.25504448f
#define ONESH2 0x3C003C00u

// ---------------- scratch ----------------
__device__ __half g_qnt[N_TOK * C_DIM];
__device__ __half g_vnt[N_TOK * C_DIM];
__device__ __half g_qt [N_TOK * C_DIM];
__device__ __half g_kt [N_TOK * C_DIM];
__device__ __half g_vt [N_TOK * C_DIM];
__device__ __half g_aot[N_TOK * C_DIM];
__device__ __half g_wh [4 * C_DIM * C_DIM];
__device__ float g_cs[C_DIM], g_cq[C_DIM];

// ---------------- helpers ----------------
__device__ __forceinline__ float ex2(float x) {
    float r; asm("ex2.approx.ftz.f32 %0, %1;" : "=f"(r) : "f"(x)); return r;
}
__device__ __forceinline__ unsigned h2ex2(unsigned x) {
    unsigned r; asm("ex2.approx.f16x2 %0, %1;" : "=r"(r) : "r"(x)); return r;
}
__device__ __forceinline__ unsigned packh2(float lo, float hi) {
    unsigned u; asm("cvt.rn.f16x2.f32 %0, %1, %2;" : "=r"(u) : "f"(hi), "f"(lo)); return u;
}
__device__ __forceinline__ unsigned hsub2(unsigned a, unsigned b) {
    unsigned r; asm("sub.rn.f16x2 %0, %1, %2;" : "=r"(r) : "r"(a), "r"(b)); return r;
}
// f32-accumulator MMA
__device__ __forceinline__ void mma16816(float* d, const unsigned* a, unsigned b0, unsigned b1) {
    asm volatile(
        "mma.sync.aligned.m16n8k16.row.col.f32.f16.f16.f32 "
        "{%0,%1,%2,%3}, {%4,%5,%6,%7}, {%8,%9}, {%0,%1,%2,%3};"
        : "+f"(d[0]), "+f"(d[1]), "+f"(d[2]), "+f"(d[3])
        : "r"(a[0]), "r"(a[1]), "r"(a[2]), "r"(a[3]), "r"(b0), "r"(b1));
}
__device__ __forceinline__ void mma16816_z(float* d, const unsigned* a, unsigned b0, unsigned b1) {
    asm volatile(
        "mma.sync.aligned.m16n8k16.row.col.f32.f16.f16.f32 "
        "{%0,%1,%2,%3}, {%4,%5,%6,%7}, {%8,%9}, {%10,%10,%10,%10};"
        : "=f"(d[0]), "=f"(d[1]), "=f"(d[2]), "=f"(d[3])
        : "r"(a[0]), "r"(a[1]), "r"(a[2]), "r"(a[3]), "r"(b0), "r"(b1), "f"(0.f));
}
__device__ __forceinline__ unsigned su32(const void* p) {
    return (unsigned)__cvta_generic_to_shared(p);
}
__device__ __forceinline__ void ldsm4u(unsigned* r, unsigned a) {
    asm volatile("ldmatrix.sync.aligned.m8n8.x4.shared.b16 {%0,%1,%2,%3}, [%4];"
                 : "=r"(r[0]), "=r"(r[1]), "=r"(r[2]), "=r"(r[3]) : "r"(a));
}
__device__ __forceinline__ void ldsm4tu(unsigned* r, unsigned a) {
    asm volatile("ldmatrix.sync.aligned.m8n8.x4.trans.shared.b16 {%0,%1,%2,%3}, [%4];"
                 : "=r"(r[0]), "=r"(r[1]), "=r"(r[2]), "=r"(r[3]) : "r"(a));
}
__device__ __forceinline__ void cp16(void* smem, const void* gmem) {
    unsigned sa = (unsigned)__cvta_generic_to_shared(smem);
    asm volatile("cp.async.cg.shared.global [%0], [%1], 16;" :: "r"(sa), "l"(gmem) : "memory");
}
#define CP_COMMIT asm volatile("cp.async.commit_group;" ::: "memory")
#define CP_WAIT1  asm volatile("cp.async.wait_group 1;" ::: "memory")
#define CP_WAIT0  asm volatile("cp.async.wait_group 0;" ::: "memory")

// ---------------------------------------------------------------------------
// Fused: per-channel stats (blocks 0..511) + weight fp16 rounding (512..1023).
// ---------------------------------------------------------------------------
__global__ __launch_bounds__(256) void stats_weights(const float* __restrict__ x,
                                                     const float* __restrict__ wq,
                                                     const float* __restrict__ wk,
                                                     const float* __restrict__ wv,
                                                     const float* __restrict__ wo) {
    int b = blockIdx.x;
    if (b < C_DIM) {
        __shared__ float sh[16];
        const float4* p = (const float4*)(x + (size_t)b * N_TOK);
        float s = 0.f, sq = 0.f;
        #pragma unroll
        for (int i = threadIdx.x; i < N_TOK / 4; i += 256) {
            float4 v = p[i];
            s  += (v.x + v.y) + (v.z + v.w);
            sq += v.x * v.x + v.y * v.y + v.z * v.z + v.w * v.w;
        }
        #pragma unroll
        for (int off = 16; off > 0; off >>= 1) {
            s  += __shfl_down_sync(0xffffffffu, s,  off);
            sq += __shfl_down_sync(0xffffffffu, sq, off);
        }
        int wr = threadIdx.x >> 5, lane = threadIdx.x & 31;
        if (lane == 0) { sh[wr] = s; sh[8 + wr] = sq; }
        __syncthreads();
        if (threadIdx.x == 0) {
            float ts = 0.f, tq = 0.f;
            #pragma unroll
            for (int i = 0; i < 8; ++i) { ts += sh[i]; tq += sh[8 + i]; }
            g_cs[b] = ts; g_cq[b] = tq;
        }
    } else {
        int base = (b - C_DIM) * 512;
        #pragma unroll
        for (int it = 0; it < 2; ++it) {
            int i = base + threadIdx.x + it * 256;
            int sel = i >> 16, loc = i & 65535;
            const float4* src = (const float4*)(sel == 0 ? wq : sel == 1 ? wk : sel == 2 ? wv : wo);
            float sc = (sel == 0) ? ALPHA : 1.f;
            float4 v = src[loc];
            uint2 o;
            o.x = packh2(v.x * sc, v.y * sc);
            o.y = packh2(v.z * sc, v.w * sc);
            *(uint2*)&g_wh[(size_t)i * 4] = o;
        }
    }
}

// ---------------------------------------------------------------------------
// GN apply + transpose with inline analytic finalize. grid (N_TOK/64, 4)
// ---------------------------------------------------------------------------
__global__ __launch_bounds__(256) void apply_tr(const float* __restrict__ x,
                                                const float* __restrict__ w,
                                                const float* __restrict__ b) {
    __shared__ float a1s[C_DIM], c1s[C_DIM], avs[C_DIM], cvs[C_DIM];
    __shared__ __half sq[64][132];
    __shared__ __half sv[64][132];
    int tid = threadIdx.x;

    if (tid < 32) {
        int g = tid;
        const float inv = 1.f / (float)N_TOK;
        float m1 = 0.f, E1 = 0.f;
        #pragma unroll
        for (int c = 0; c < 16; ++c) {
            int ch = g * 16 + c;
            m1 += g_cs[ch] * inv;
            E1 += g_cq[ch] * inv;
        }
        m1 *= (1.f / 16.f); E1 *= (1.f / 16.f);
        float is1 = rsqrtf(E1 - m1 * m1 + 1e-6f);
        float m2 = 0.f, E2 = 0.f;
        #pragma unroll
        for (int c = 0; c < 16; ++c) {
            int ch = g * 16 + c;
            float mc = g_cs[ch] * inv, Ec = g_cq[ch] * inv;
            float a1 = w[ch] * is1;
            float c1 = b[ch] - m1 * a1;
            a1s[ch] = a1; c1s[ch] = c1;
            m2 += a1 * mc + c1;
            E2 += a1 * a1 * Ec + 2.f * a1 * c1 * mc + c1 * c1;
        }
        m2 *= (1.f / 16.f); E2 *= (1.f / 16.f);
        float is2 = rsqrtf(E2 - m2 * m2 + 1e-6f);
        #pragma unroll
        for (int c = 0; c < 16; ++c) {
            int ch = g * 16 + c;
            float a2 = w[ch] * is2;
            float c2 = b[ch] - m2 * a2;
            avs[ch] = a2 * a1s[ch];
            cvs[ch] = a2 * c1s[ch] + c2;
        }
    }
    __syncthreads();

    int n0 = blockIdx.x * 64;
    int cc = blockIdx.y;
    #pragma unroll
    for (int i = 0; i < 32; ++i) {
        int idx = tid + i * 256;
        int t = idx & 63, ci = idx >> 6;
        int c = cc * 128 + ci;
        float v = x[(size_t)c * N_TOK + n0 + t];
        sq[t][ci] = __float2half_rn(v * a1s[c] + c1s[c]);
        sv[t][ci] = __float2half_rn(v * avs[c] + cvs[c]);
    }
    __syncthreads();
    #pragma unroll
    for (int i = 0; i < 16; ++i) {
        int idx = tid + i * 256;
        int t = idx >> 6, j = idx & 63;
        __half2 q2 = __halves2half2(sq[t][2 * j], sq[t][2 * j + 1]);
        __half2 v2 = __halves2half2(sv[t][2 * j], sv[t][2 * j + 1]);
        *(__half2*)&g_qnt[(size_t)(n0 + t) * 512 + cc * 128 + 2 * j] = q2;
        *(__half2*)&g_vnt[(size_t)(n0 + t) * 512 + cc * 128 + 2 * j] = v2;
    }
}

// ---------------------------------------------------------------------------
// fp16 GEMM: C[tok][outch] = Xt * W^T + bias.
// Block 64(tok) x 128(ch), BK=32, 256 threads, warp tile 32x32.
// Fragment loads via ldmatrix.x4 (8 per mainloop iter vs 32 scalar LDS).
// ---------------------------------------------------------------------------
template<int FIN>
__global__ __launch_bounds__(256, 2) void gemm_h(const float* __restrict__ b0p,
                                                 const float* __restrict__ b1p,
                                                 const float* __restrict__ b2p,
                                                 const float* __restrict__ resid,
                                                 float* __restrict__ OutF) {
    __shared__ __half As[2][64 * 40];
    __shared__ __half Bs[2][128 * 40];

    int tid = threadIdx.x;
    int warp = tid >> 5, lane = tid & 31;
    int g = lane >> 2, qq = lane & 3;
    int wm = warp >> 2, wn = warp & 3;
    int m0 = blockIdx.x * 64;
    int n0 = blockIdx.y * 128;

    int z = FIN ? 3 : (int)blockIdx.z;
    const __half* W  = g_wh + (size_t)z * (C_DIM * C_DIM);
    const __half* Xt = FIN ? g_aot : (z == 0 ? g_qnt : g_vnt);
    const float* bias = FIN ? b0p : (z == 0 ? b0p : (z == 1 ? b1p : b2p));
    __half* OutH = z == 0 ? g_qt : (z == 1 ? g_kt : g_vt);

    float acc[2][4][4];
    #pragma unroll
    for (int i = 0; i < 2; ++i)
        #pragma unroll
        for (int j = 0; j < 4; ++j)
            #pragma unroll
            for (int r = 0; r < 4; ++r) acc[i][j][r] = 0.f;

    // hoisted ldmatrix lane offsets (bytes)
    // A: rows wm*32 + mi*16 + (lane&15), col halves (lane>>4)*8 (+16 per kk)
    unsigned aoff[2], boff[4];
    #pragma unroll
    for (int mi = 0; mi < 2; ++mi)
        aoff[mi] = ((wm * 32 + mi * 16 + (lane & 15)) * 40 + ((lane >> 4) << 3)) * 2;
    // B: rows wn*32 + ni*8 + (lane&7), col halves (lane>>3)*8 (covers BK=32)
    #pragma unroll
    for (int ni = 0; ni < 4; ++ni)
        boff[ni] = ((wn * 32 + ni * 8 + (lane & 7)) * 40 + ((lane >> 3) << 3)) * 2;
    unsigned Asu[2] = { su32(&As[0][0]), su32(&As[1][0]) };
    unsigned Bsu[2] = { su32(&Bs[0][0]), su32(&Bs[1][0]) };

    #define GLOAD(st, k0)                                                        \
    {                                                                            \
        { int m = tid >> 2, q = tid & 3;                                         \
          cp16(&As[st][m * 40 + q * 8], &Xt[(size_t)(m0 + m) * 512 + (k0) + q * 8]); } \
        _Pragma("unroll")                                                        \
        for (int i = 0; i < 2; ++i) {                                            \
            int idx = tid + i * 256; int n = idx >> 2, q = idx & 3;              \
            cp16(&Bs[st][n * 40 + q * 8], &W[(size_t)(n0 + n) * 512 + (k0) + q * 8]); \
        }                                                                        \
    }

    GLOAD(0, 0); CP_COMMIT;

    #pragma unroll 1
    for (int kt = 0; kt < 16; ++kt) {
        int s = kt & 1;
        if (kt < 15) { GLOAD(s ^ 1, (kt + 1) * 32); CP_COMMIT; CP_WAIT1; }
        else         { CP_WAIT0; }
        __syncthreads();

        // B fragments: one ldsm4 per ni covers full BK=32
        unsigned bb[4][4];
        #pragma unroll
        for (int ni = 0; ni < 4; ++ni)
            ldsm4u(bb[ni], Bsu[s] + boff[ni]);

        #pragma unroll
        for (int kk = 0; kk < 2; ++kk) {
            unsigned a[2][4];
            ldsm4u(a[0], Asu[s] + aoff[0] + kk * 32);
            ldsm4u(a[1], Asu[s] + aoff[1] + kk * 32);
            #pragma unroll
            for (int mi = 0; mi < 2; ++mi)
                #pragma unroll
                for (int ni = 0; ni < 4; ++ni)
                    mma16816(acc[mi][ni], a[mi], bb[ni][2 * kk], bb[ni][2 * kk + 1]);
        }
        __syncthreads();
    }
    #undef GLOAD

    const float IS2 = 0.70710678118654752f;
    float bscale = (!FIN && z == 0) ? ALPHA : 1.f;
    #pragma unroll
    for (int mi = 0; mi < 2; ++mi) {
        int t = m0 + wm * 32 + mi * 16 + g;
        #pragma unroll
        for (int ni = 0; ni < 4; ++ni) {
            int ch = n0 + wn * 32 + ni * 8 + 2 * qq;
            float bb0 = bias[ch] * bscale, bb1 = bias[ch + 1] * bscale;
            float c0 = acc[mi][ni][0] + bb0, c1 = acc[mi][ni][1] + bb1;
            float c2 = acc[mi][ni][2] + bb0, c3 = acc[mi][ni][3] + bb1;
            if (FIN) {
                size_t i00 = (size_t)ch * N_TOK + t;
                size_t i10 = (size_t)(ch + 1) * N_TOK + t;
                OutF[i00]     = (c0 + resid[i00])     * IS2;
                OutF[i10]     = (c1 + resid[i10])     * IS2;
                OutF[i00 + 8] = (c2 + resid[i00 + 8]) * IS2;
                OutF[i10 + 8] = (c3 + resid[i10 + 8]) * IS2;
            } else {
                *(unsigned*)&OutH[(size_t)t * 512 + ch]       = packh2(c0, c1);
                *(unsigned*)&OutH[(size_t)(t + 8) * 512 + ch] = packh2(c2, c3);
            }
        }
    }
}

// ---------------------------------------------------------------------------
// Flash attention fp16 (round-10 version, best known: 133us).
// CTA = 64 queries x head (4 warps x 16 q-rows), 128-key tiles;
// RZ-init MMAs; f16x2 subtract+exp; ones-MMA l; hoisted ldmatrix bases.
// ---------------------------------------------------------------------------
__global__ __launch_bounds__(128, 4) void attn_h() {
    __shared__ __half Ks[2][128 * 40];
    __shared__ __half Vs[2][128 * 40];

    int tid = threadIdx.x;
    int lane = tid & 31;
    int w = tid >> 5;
    int g = lane >> 2, qq = lane & 3;
    int h = blockIdx.y;
    int hb = h * HDIM;
    int q0 = blockIdx.x * 64 + w * 16;

    unsigned qa[2][4];
    #pragma unroll
    for (int kk = 0; kk < 2; ++kk) {
        const __half* qp = &g_qt[(size_t)(q0 + g) * 512 + hb + kk * 16 + 2 * qq];
        qa[kk][0] = *(const unsigned*)qp;
        qa[kk][1] = *(const unsigned*)(qp + 8 * 512);
        qa[kk][2] = *(const unsigned*)(qp + 8);
        qa[kk][3] = *(const unsigned*)(qp + 8 * 512 + 8);
    }

    float o[4][4];
    #pragma unroll
    for (int nd = 0; nd < 4; ++nd)
        #pragma unroll
        for (int e = 0; e < 4; ++e) o[nd][e] = 0.f;
    float m0 = -1e30f, m1 = -1e30f, l0 = 0.f, l1 = 0.f;

    int kfrag = ((lane & 7) * 40 + ((lane >> 3) << 3)) * 2;
    int vfrag = ((lane & 15) * 40 + ((lane >> 4) << 3)) * 2;
    unsigned ksu[2] = { su32(&Ks[0][0]) + kfrag, su32(&Ks[1][0]) + kfrag };
    unsigned vsu[2] = { su32(&Vs[0][0]) + vfrag, su32(&Vs[1][0]) + vfrag };

    #define APRE(st, kt0)                                                        \
    {                                                                            \
        _Pragma("unroll")                                                        \
        for (int i = 0; i < 4; ++i) {                                            \
            int idx = tid + i * 128; int row = idx >> 2, q = idx & 3;            \
            cp16(&Ks[st][row * 40 + q * 8],                                      \
                 &g_kt[(size_t)((kt0) + row) * 512 + hb + q * 8]);               \
            cp16(&Vs[st][row * 40 + q * 8],                                      \
                 &g_vt[(size_t)((kt0) + row) * 512 + hb + q * 8]);               \
        }                                                                        \
    }

    APRE(0, 0); CP_COMMIT;

    #pragma unroll 1
    for (int it = 0; it < 32; ++it) {
        int s = it & 1;
        if (it < 31) { APRE(s ^ 1, (it + 1) * 128); CP_COMMIT; CP_WAIT1; }
        else         { CP_WAIT0; }
        __syncthreads();

        // S = Q K^T (16q x 128k), RZ-init f32 accumulators
        float sc[16][4];
        #pragma unroll
        for (int nj = 0; nj < 16; ++nj) {
            unsigned kb[4];
            ldsm4u(kb, ksu[s] + nj * (8 * 40 * 2));
            mma16816_z(sc[nj], qa[0], kb[0], kb[1]);
            mma16816  (sc[nj], qa[1], kb[2], kb[3]);
        }

        // row max (rows g, g+8)
        float mx0 = -1e30f, mx1 = -1e30f;
        #pragma unroll
        for (int nj = 0; nj < 16; ++nj) {
            mx0 = fmaxf(mx0, fmaxf(sc[nj][0], sc[nj][1]));
            mx1 = fmaxf(mx1, fmaxf(sc[nj][2], sc[nj][3]));
        }
        mx0 = fmaxf(mx0, __shfl_xor_sync(0xffffffffu, mx0, 1));
        mx0 = fmaxf(mx0, __shfl_xor_sync(0xffffffffu, mx0, 2));
        mx1 = fmaxf(mx1, __shfl_xor_sync(0xffffffffu, mx1, 1));
        mx1 = fmaxf(mx1, __shfl_xor_sync(0xffffffffu, mx1, 2));
        float nm0 = fmaxf(m0, mx0), nm1 = fmaxf(m1, mx1);
        float cr0 = ex2(m0 - nm0), cr1 = ex2(m1 - nm1);
        m0 = nm0; m1 = nm1;
        #pragma unroll
        for (int nd = 0; nd < 4; ++nd) {
            o[nd][0] *= cr0; o[nd][1] *= cr0;
            o[nd][2] *= cr1; o[nd][3] *= cr1;
        }
        unsigned nm00 = packh2(nm0, nm0), nm11 = packh2(nm1, nm1);

        // per 16-key block: P = exp2(S - m) via f16x2 sub+exp; l-MMA; PV
        float lacc[4];
        #pragma unroll
        for (int kk = 0; kk < 8; ++kk) {
            unsigned ph[4];
            ph[0] = h2ex2(hsub2(packh2(sc[2*kk][0],   sc[2*kk][1]),   nm00));
            ph[1] = h2ex2(hsub2(packh2(sc[2*kk][2],   sc[2*kk][3]),   nm11));
            ph[2] = h2ex2(hsub2(packh2(sc[2*kk+1][0], sc[2*kk+1][1]), nm00));
            ph[3] = h2ex2(hsub2(packh2(sc[2*kk+1][2], sc[2*kk+1][3]), nm11));
            if (kk == 0) mma16816_z(lacc, ph, ONESH2, ONESH2);
            else         mma16816  (lacc, ph, ONESH2, ONESH2);
            unsigned v0[4], v1[4];
            unsigned vb = vsu[s] + kk * (16 * 40 * 2);
            ldsm4tu(v0, vb);
            ldsm4tu(v1, vb + 32);
            mma16816(o[0], ph, v0[0], v0[1]);
            mma16816(o[1], ph, v0[2], v0[3]);
            mma16816(o[2], ph, v1[0], v1[1]);
            mma16816(o[3], ph, v1[2], v1[3]);
        }
        l0 = l0 * cr0 + lacc[0];
        l1 = l1 * cr1 + lacc[2];
        __syncthreads();
    }
    #undef APRE

    float i0 = 1.f / l0, i1 = 1.f / l1;
    #pragma unroll
    for (int nd = 0; nd < 4; ++nd) {
        int d = hb + nd * 8 + 2 * qq;
        *(unsigned*)&g_aot[(size_t)(q0 + g) * 512 + d]     = packh2(o[nd][0] * i0, o[nd][1] * i0);
        *(unsigned*)&g_aot[(size_t)(q0 + g + 8) * 512 + d] = packh2(o[nd][2] * i1, o[nd][3] * i1);
    }
}

// ---------------------------------------------------------------------------
// Launch
// ---------------------------------------------------------------------------
extern "C" void kernel_launch(void* const* d_in, const int* in_sizes, int n_in,
                              void* d_out, int out_size) {
    const float* x   = (const float*)d_in[0];
    const float* gnw = (const float*)d_in[1];
    const float* gnb = (const float*)d_in[2];
    const float* wq  = (const float*)d_in[3];
    const float* bq  = (const float*)d_in[4];
    const float* wk  = (const float*)d_in[5];
    const float* bk  = (const float*)d_in[6];
    const float* wv  = (const float*)d_in[7];
    const float* bv  = (const float*)d_in[8];
    const float* wo  = (const float*)d_in[9];
    const float* bo  = (const float*)d_in[10];
    float* out = (float*)d_out;

    stats_weights<<<1024, 256>>>(x, wq, wk, wv, wo);

    dim3 at(N_TOK / 64, 4);
    apply_tr<<<at, 256>>>(x, gnw, gnb);

    dim3 gqkv(N_TOK / 64, C_DIM / 128, 3);      // 768 CTAs
    gemm_h<0><<<gqkv, 256>>>(bq, bk, bv, nullptr, nullptr);

    dim3 ag(N_TOK / 64, HEADS);                 // (64, 16) = 1024 CTAs
    attn_h<<<ag, 128>>>();

    dim3 go(N_TOK / 64, C_DIM / 128, 1);        // 256 CTAs
    gemm_h<1><<<go, 256>>>(bo, nullptr, nullptr, x, out);
}